// round 12
// baseline (speedup 1.0000x reference)
#include <cuda_runtime.h>
#include <math.h>
#include <stdint.h>

// Problem constants
#define B_   64
#define IN_  512
#define M_   1024
#define NG   6          // q,k,v,i,f,o
#define NSPLIT 4
#define KSL  (IN_ / NSPLIT)   // 128
#define BM   (B_ * M_)

// scratch
__device__ float g_gates[NG * B_ * M_];          // [gate][b][m]
__device__ float g_part[NSPLIT * B_ * NG * M_];  // [s][b][n_global]

// update_C TMA pipeline geometry
#define ROWS_PER_TILE 4
#define NTILES 16                       // 64 rows / 4
#define NBUF 4
#define TILE_FLOATS (ROWS_PER_TILE * M_)     // 4096
#define TILE_BYTES  (TILE_FLOATS * 4)        // 16384
#define DSMEM_BYTES (NBUF * TILE_BYTES + 2 * M_ * 4)   // bufs + sk + sq = 73728

// ---------------------------------------------------------------------------
// small PTX helpers
// ---------------------------------------------------------------------------
__device__ __forceinline__ uint32_t f2tf32(float f) {
    uint32_t u;
    asm("cvt.rna.tf32.f32 %0, %1;" : "=r"(u) : "f"(f));
    return u;
}

__device__ __forceinline__ void mma_tf32(float* c, const uint32_t* a, const uint32_t* b) {
    asm("mma.sync.aligned.m16n8k8.row.col.f32.tf32.tf32.f32 "
        "{%0,%1,%2,%3},{%4,%5,%6,%7},{%8,%9},{%0,%1,%2,%3};"
        : "+f"(c[0]), "+f"(c[1]), "+f"(c[2]), "+f"(c[3])
        : "r"(a[0]), "r"(a[1]), "r"(a[2]), "r"(a[3]),
          "r"(b[0]), "r"(b[1]));
}

__device__ __forceinline__ uint32_t sptr(const void* p) {
    return (uint32_t)__cvta_generic_to_shared(p);
}

__device__ __forceinline__ void mbar_init(uint32_t a, uint32_t cnt) {
    asm volatile("mbarrier.init.shared.b64 [%0], %1;" :: "r"(a), "r"(cnt) : "memory");
}
__device__ __forceinline__ void mbar_expect_tx(uint32_t a, uint32_t bytes) {
    asm volatile("mbarrier.arrive.expect_tx.shared.b64 _, [%0], %1;"
                 :: "r"(a), "r"(bytes) : "memory");
}
__device__ __forceinline__ void mbar_wait(uint32_t a, uint32_t parity) {
    asm volatile(
        "{\n\t.reg .pred P;\n"
        "W%=:\n\t"
        "mbarrier.try_wait.parity.acquire.cta.shared::cta.b64 P, [%0], %1, 0x989680;\n\t"
        "@!P bra W%=;\n\t}"
        :: "r"(a), "r"(parity) : "memory");
}
__device__ __forceinline__ void bulk_load(uint32_t dst_smem, const void* src, uint32_t bytes,
                                          uint32_t mbar) {
    asm volatile("cp.async.bulk.shared::cta.global.mbarrier::complete_tx::bytes "
                 "[%0], [%1], %2, [%3];"
                 :: "r"(dst_smem), "l"(src), "r"(bytes), "r"(mbar) : "memory");
}
__device__ __forceinline__ void bulk_store(void* dst, uint32_t src_smem, uint32_t bytes) {
    asm volatile("cp.async.bulk.global.shared::cta.bulk_group [%0], [%1], %2;"
                 :: "l"(dst), "r"(src_smem), "r"(bytes) : "memory");
}
__device__ __forceinline__ void bulk_commit() {
    asm volatile("cp.async.bulk.commit_group;" ::: "memory");
}
template <int N>
__device__ __forceinline__ void bulk_wait() {
    asm volatile("cp.async.bulk.wait_group %0;" :: "n"(N) : "memory");
}
__device__ __forceinline__ void fence_async() {
    asm volatile("fence.proxy.async;" ::: "memory");
}

__device__ __forceinline__ float sigmoidf_(float v) {
    return 1.f / (1.f + __expf(-v));
}

// ---------------------------------------------------------------------------
// Kernel 1a: split-K TF32 tensor-core GEMM partials (R10 version, 10.6us)
// ---------------------------------------------------------------------------
__global__ __launch_bounds__(256)
void gates_mma_sk(const float* __restrict__ x,
                  const float* __restrict__ Wq, const float* __restrict__ Wk,
                  const float* __restrict__ Wv, const float* __restrict__ Wi,
                  const float* __restrict__ Wf, const float* __restrict__ Wo)
{
    const int n_global0 = blockIdx.x * 64;
    const int gate      = n_global0 >> 10;
    const int n_local0  = n_global0 & (M_ - 1);
    const int s         = blockIdx.y;
    const int k_base    = s * KSL;

    const float* W;
    switch (gate) {
        case 0: W = Wq; break;
        case 1: W = Wk; break;
        case 2: W = Wv; break;
        case 3: W = Wi; break;
        case 4: W = Wf; break;
        default: W = Wo; break;
    }

    __shared__ uint32_t Xs[2][64][36];
    __shared__ uint32_t Ws[2][64][36];

    const int tid  = threadIdx.x;
    const int wid  = tid >> 5;
    const int lane = tid & 31;
    const int g    = lane >> 2;
    const int tig  = lane & 3;
    const int warp_m = wid & 1;
    const int warp_n = wid >> 1;

    const int lrow0 = tid >> 3;
    const int lrow1 = lrow0 + 32;
    const int lcol  = (tid & 7) * 4;

    const float* xg0 = x + lrow0 * IN_ + k_base + lcol;
    const float* xg1 = x + lrow1 * IN_ + k_base + lcol;
    const float* wg0 = W + (n_local0 + lrow0) * IN_ + k_base + lcol;
    const float* wg1 = W + (n_local0 + lrow1) * IN_ + k_base + lcol;

    float acc[2][2][4];
    #pragma unroll
    for (int mt = 0; mt < 2; mt++)
        #pragma unroll
        for (int nt = 0; nt < 2; nt++)
            #pragma unroll
            for (int e = 0; e < 4; e++) acc[mt][nt][e] = 0.f;

    float4 xr0, xr1, wr0, wr1;
    xr0 = *(const float4*)xg0;
    xr1 = *(const float4*)xg1;
    wr0 = *(const float4*)wg0;
    wr1 = *(const float4*)wg1;

    {
        uint4 u;
        u.x = f2tf32(xr0.x); u.y = f2tf32(xr0.y); u.z = f2tf32(xr0.z); u.w = f2tf32(xr0.w);
        *(uint4*)&Xs[0][lrow0][lcol] = u;
        u.x = f2tf32(xr1.x); u.y = f2tf32(xr1.y); u.z = f2tf32(xr1.z); u.w = f2tf32(xr1.w);
        *(uint4*)&Xs[0][lrow1][lcol] = u;
        u.x = f2tf32(wr0.x); u.y = f2tf32(wr0.y); u.z = f2tf32(wr0.z); u.w = f2tf32(wr0.w);
        *(uint4*)&Ws[0][lrow0][lcol] = u;
        u.x = f2tf32(wr1.x); u.y = f2tf32(wr1.y); u.z = f2tf32(wr1.z); u.w = f2tf32(wr1.w);
        *(uint4*)&Ws[0][lrow1][lcol] = u;
    }
    __syncthreads();

    int buf = 0;
    #pragma unroll 1
    for (int it = 0; it < KSL / 32; it++) {
        if (it < KSL / 32 - 1) {
            const int k0 = (it + 1) * 32;
            xr0 = *(const float4*)(xg0 + k0);
            xr1 = *(const float4*)(xg1 + k0);
            wr0 = *(const float4*)(wg0 + k0);
            wr1 = *(const float4*)(wg1 + k0);
        }

        #pragma unroll
        for (int ks = 0; ks < 4; ks++) {
            const int ko = ks * 8;
            uint32_t af[2][4];
            #pragma unroll
            for (int mt = 0; mt < 2; mt++) {
                const int r = warp_m * 32 + mt * 16 + g;
                af[mt][0] = Xs[buf][r][ko + tig];
                af[mt][1] = Xs[buf][r + 8][ko + tig];
                af[mt][2] = Xs[buf][r][ko + tig + 4];
                af[mt][3] = Xs[buf][r + 8][ko + tig + 4];
            }
            uint32_t bfr[2][2];
            #pragma unroll
            for (int nt = 0; nt < 2; nt++) {
                const int c = warp_n * 16 + nt * 8 + g;
                bfr[nt][0] = Ws[buf][c][ko + tig];
                bfr[nt][1] = Ws[buf][c][ko + tig + 4];
            }
            #pragma unroll
            for (int mt = 0; mt < 2; mt++)
                #pragma unroll
                for (int nt = 0; nt < 2; nt++)
                    mma_tf32(acc[mt][nt], af[mt], bfr[nt]);
        }

        if (it < KSL / 32 - 1) {
            const int nb = buf ^ 1;
            uint4 u;
            u.x = f2tf32(xr0.x); u.y = f2tf32(xr0.y); u.z = f2tf32(xr0.z); u.w = f2tf32(xr0.w);
            *(uint4*)&Xs[nb][lrow0][lcol] = u;
            u.x = f2tf32(xr1.x); u.y = f2tf32(xr1.y); u.z = f2tf32(xr1.z); u.w = f2tf32(xr1.w);
            *(uint4*)&Xs[nb][lrow1][lcol] = u;
            u.x = f2tf32(wr0.x); u.y = f2tf32(wr0.y); u.z = f2tf32(wr0.z); u.w = f2tf32(wr0.w);
            *(uint4*)&Ws[nb][lrow0][lcol] = u;
            u.x = f2tf32(wr1.x); u.y = f2tf32(wr1.y); u.z = f2tf32(wr1.z); u.w = f2tf32(wr1.w);
            *(uint4*)&Ws[nb][lrow1][lcol] = u;
            __syncthreads();
            buf = nb;
        }
    }

    float* outp = g_part + (size_t)s * ((size_t)B_ * NG * M_);
    #pragma unroll
    for (int mt = 0; mt < 2; mt++) {
        const int r0 = warp_m * 32 + mt * 16 + g;
        #pragma unroll
        for (int nt = 0; nt < 2; nt++) {
            const int ncol = n_global0 + warp_n * 16 + nt * 8 + 2 * tig;
            *(float2*)&outp[(size_t)r0 * (NG * M_) + ncol] =
                make_float2(acc[mt][nt][0], acc[mt][nt][1]);
            *(float2*)&outp[(size_t)(r0 + 8) * (NG * M_) + ncol] =
                make_float2(acc[mt][nt][2], acc[mt][nt][3]);
        }
    }
}

// ---------------------------------------------------------------------------
// Kernel 1b: reduce partials + bias + activation -> g_gates[gate][b][m]
// ---------------------------------------------------------------------------
__global__ __launch_bounds__(256)
void gates_reduce(const float* __restrict__ bq, const float* __restrict__ bk,
                  const float* __restrict__ bv, const float* __restrict__ bi,
                  const float* __restrict__ bf, const float* __restrict__ bo)
{
    const int idx = blockIdx.x * 256 + threadIdx.x;
    const int b   = idx / (NG * M_ / 4);
    const int c4  = idx % (NG * M_ / 4);
    const int n   = c4 * 4;
    const int gate = n >> 10;
    const int nl   = n & (M_ - 1);

    const float* bias;
    switch (gate) {
        case 0: bias = bq; break;
        case 1: bias = bk; break;
        case 2: bias = bv; break;
        case 3: bias = bi; break;
        case 4: bias = bf; break;
        default: bias = bo; break;
    }

    float4 acc = *(const float4*)&g_part[((size_t)0 * B_ + b) * (NG * M_) + n];
    #pragma unroll
    for (int s = 1; s < NSPLIT; s++) {
        float4 p = *(const float4*)&g_part[((size_t)s * B_ + b) * (NG * M_) + n];
        acc.x += p.x; acc.y += p.y; acc.z += p.z; acc.w += p.w;
    }
    const float4 bv4 = *(const float4*)&bias[nl];
    acc.x += bv4.x; acc.y += bv4.y; acc.z += bv4.z; acc.w += bv4.w;

    if (gate == 1) {
        acc.x *= 0.03125f; acc.y *= 0.03125f; acc.z *= 0.03125f; acc.w *= 0.03125f;
    } else if (gate == 3) {
        acc.x = __expf(acc.x); acc.y = __expf(acc.y);
        acc.z = __expf(acc.z); acc.w = __expf(acc.w);
    } else if (gate >= 4) {
        acc.x = sigmoidf_(acc.x);
        acc.y = sigmoidf_(acc.y);
        acc.z = sigmoidf_(acc.z);
        acc.w = sigmoidf_(acc.w);
    }
    *(float4*)&g_gates[(size_t)gate * BM + b * M_ + nl] = acc;
}

// ---------------------------------------------------------------------------
// Kernel 2: TMA-pipelined C update.
// grid = (16, 64): blockIdx.y = batch, blockIdx.x = 64-row chunk.
// 4 smem buffers of 4 rows (16KB), depth-2 bulk-load prefetch (mbarrier),
// in-place compute (LDS -> FMA -> STS), bulk-store with bulk_group tracking.
// Warp w handles row (w>>1), half (w&1) of each 4-row tile; dot halves are
// combined in smem. Prologue: n_t + denom from g_gates (R10 structure).
// ---------------------------------------------------------------------------
__global__ __launch_bounds__(256)
void update_C(const float* __restrict__ Cprev, const float* __restrict__ nprev,
              float* __restrict__ Cout, float* __restrict__ out_h,
              float* __restrict__ out_n)
{
    const int b  = blockIdx.y;
    const int m0 = blockIdx.x * 64;

    extern __shared__ float dsm[];
    float* bufs = dsm;                       // NBUF * TILE_FLOATS
    float* sk   = dsm + NBUF * TILE_FLOATS;  // 1024
    float* sq   = sk + M_;                   // 1024

    __shared__ float s_fm[64], s_cm[64], s_om[64];
    __shared__ float red[8];
    __shared__ float sred[2][8];
    __shared__ float s_inv;
    __shared__ __align__(8) uint64_t mbar[NBUF];

    const int t    = threadIdx.x;
    const int warp = t >> 5;
    const int lane = t & 31;

    const float* gq = g_gates + 0 * BM + b * M_;
    const float* gk = g_gates + 1 * BM + b * M_;
    const float* gv = g_gates + 2 * BM + b * M_;
    const float* gi = g_gates + 3 * BM + b * M_;
    const float* gf = g_gates + 4 * BM + b * M_;
    const float* go = g_gates + 5 * BM + b * M_;

    // stage k, q
    ((float4*)sk)[t] = ((const float4*)gk)[t];
    ((float4*)sq)[t] = ((const float4*)gq)[t];
    // per-row gate scalars for this block's 64 rows
    if (t < 64) {
        const int m = m0 + t;
        s_fm[t] = gf[m];
        s_cm[t] = gi[m] * gv[m];
        s_om[t] = go[m];
    }
    // mbarrier init + initial loads (tid 0)
    if (t == 0) {
        #pragma unroll
        for (int i = 0; i < NBUF; i++) mbar_init(sptr(&mbar[i]), 1);
    }
    __syncthreads();

    const uint32_t buf_sa = sptr(bufs);
    const float* cbase = Cprev + ((size_t)b * M_ + m0) * M_;
    float*       obase = Cout  + ((size_t)b * M_ + m0) * M_;

    if (t == 0) {
        #pragma unroll
        for (int j = 0; j < 2; j++) {
            mbar_expect_tx(sptr(&mbar[j]), TILE_BYTES);
            bulk_load(buf_sa + j * TILE_BYTES,
                      cbase + (size_t)j * TILE_FLOATS, TILE_BYTES,
                      sptr(&mbar[j]));
        }
    }

    // --- denom prologue (overlaps with first TMA loads) ---
    {
        float4 f4 = ((const float4*)gf)[t];
        float4 i4 = ((const float4*)gi)[t];
        float4 p4 = ((const float4*)(nprev + b * M_))[t];
        float4 k4 = ((const float4*)sk)[t];
        float4 q4 = ((const float4*)sq)[t];
        float4 n4;
        n4.x = fmaf(f4.x, p4.x, i4.x * k4.x);
        n4.y = fmaf(f4.y, p4.y, i4.y * k4.y);
        n4.z = fmaf(f4.z, p4.z, i4.z * k4.z);
        n4.w = fmaf(f4.w, p4.w, i4.w * k4.w);
        if (blockIdx.x == 0)
            ((float4*)(out_n + b * M_))[t] = n4;
        float part = n4.x * q4.x + n4.y * q4.y + n4.z * q4.z + n4.w * q4.w;
        #pragma unroll
        for (int off = 16; off; off >>= 1)
            part += __shfl_xor_sync(0xffffffffu, part, off);
        if (lane == 0) red[warp] = part;
        __syncthreads();
        if (t == 0) {
            float d = red[0] + red[1] + red[2] + red[3]
                    + red[4] + red[5] + red[6] + red[7];
            s_inv = 1.0f / fmaxf(d, 1.0f);
        }
        __syncthreads();
    }
    const float inv = s_inv;

    const int r    = warp >> 1;      // row within tile (0..3)
    const int half = warp & 1;       // 0: cols 0-511, 1: cols 512-1023
    const float4* kh = (const float4*)(sk + half * 512);
    const float4* qh = (const float4*)(sq + half * 512);

    #pragma unroll 1
    for (int j = 0; j < NTILES; j++) {
        // prefetch tile j+2 (buffer freed once store j-2 completed)
        if (t == 0 && j + 2 < NTILES) {
            if (j >= 2) bulk_wait<1>();      // store j-2 done -> buffer reusable
            const int jb = (j + 2) & (NBUF - 1);
            mbar_expect_tx(sptr(&mbar[jb]), TILE_BYTES);
            bulk_load(buf_sa + jb * TILE_BYTES,
                      cbase + (size_t)(j + 2) * TILE_FLOATS, TILE_BYTES,
                      sptr(&mbar[jb]));
        }

        // wait for tile j's load
        mbar_wait(sptr(&mbar[j & (NBUF - 1)]), (j >> 2) & 1);

        // in-place compute: o = fm*c + cm*k ; dot += o*q
        const int rowm = j * ROWS_PER_TILE + r;       // row within 64
        const float fm = s_fm[rowm];
        const float cm = s_cm[rowm];
        float4* bp = (float4*)(bufs + (j & (NBUF - 1)) * TILE_FLOATS
                               + r * M_ + half * 512);
        float dot0 = 0.f, dot1 = 0.f;
        #pragma unroll
        for (int kx = 0; kx < 4; kx++) {
            const int idx = kx * 32 + lane;
            float4 c  = bp[idx];
            float4 kk = kh[idx];
            float4 qq = qh[idx];
            float4 o;
            o.x = fmaf(fm, c.x, cm * kk.x);
            o.y = fmaf(fm, c.y, cm * kk.y);
            o.z = fmaf(fm, c.z, cm * kk.z);
            o.w = fmaf(fm, c.w, cm * kk.w);
            bp[idx] = o;
            if (kx & 1) {
                dot1 = fmaf(o.x, qq.x, dot1);
                dot1 = fmaf(o.y, qq.y, dot1);
                dot1 = fmaf(o.z, qq.z, dot1);
                dot1 = fmaf(o.w, qq.w, dot1);
            } else {
                dot0 = fmaf(o.x, qq.x, dot0);
                dot0 = fmaf(o.y, qq.y, dot0);
                dot0 = fmaf(o.z, qq.z, dot0);
                dot0 = fmaf(o.w, qq.w, dot0);
            }
        }
        float dot = dot0 + dot1;
        #pragma unroll
        for (int off = 16; off; off >>= 1)
            dot += __shfl_xor_sync(0xffffffffu, dot, off);
        if (lane == 0) sred[j & 1][warp] = dot;

        __syncthreads();   // all STS + sred visible; everyone done with buf j

        if (t < ROWS_PER_TILE) {
            const float hv = sred[j & 1][2 * t] + sred[j & 1][2 * t + 1];
            out_h[b * M_ + m0 + j * ROWS_PER_TILE + t] =
                s_om[j * ROWS_PER_TILE + t] * hv * inv;
        }
        if (t == 0) {
            fence_async();   // order generic STS before async-proxy read
            bulk_store(obase + (size_t)j * TILE_FLOATS,
                       buf_sa + (j & (NBUF - 1)) * TILE_BYTES, TILE_BYTES);
            bulk_commit();
        }
    }

    if (t == 0) bulk_wait<0>();   // drain stores before CTA exit
}

// ---------------------------------------------------------------------------
// Launch. Inputs (metadata order):
// 0 x, 1 h_prev, 2 c_prev, 3 C_prev, 4 n_prev, 5 m_prev,
// 6 Wq, 7 bq, 8 Wk, 9 bk, 10 Wv, 11 bv, 12 Wi, 13 bi, 14 Wf, 15 bf, 16 Wo, 17 bo
// Output: concat(h_t [64*1024], C_t [64*1024*1024], n_t [64*1024])
// ---------------------------------------------------------------------------
extern "C" void kernel_launch(void* const* d_in, const int* in_sizes, int n_in,
                              void* d_out, int out_size)
{
    const float* x     = (const float*)d_in[0];
    const float* Cprev = (const float*)d_in[3];
    const float* nprev = (const float*)d_in[4];

    const float* Wq = (const float*)d_in[6];  const float* bq = (const float*)d_in[7];
    const float* Wk = (const float*)d_in[8];  const float* bk = (const float*)d_in[9];
    const float* Wv = (const float*)d_in[10]; const float* bv = (const float*)d_in[11];
    const float* Wi = (const float*)d_in[12]; const float* bi = (const float*)d_in[13];
    const float* Wf = (const float*)d_in[14]; const float* bf = (const float*)d_in[15];
    const float* Wo = (const float*)d_in[16]; const float* bo = (const float*)d_in[17];

    float* out   = (float*)d_out;
    float* out_h = out;                                    // [64*1024]
    float* out_C = out + (size_t)B_ * M_;                  // [64*1024*1024]
    float* out_n = out + (size_t)B_ * M_ + (size_t)B_ * M_ * M_;

    static bool attr_set = false;
    if (!attr_set) {
        cudaFuncSetAttribute(update_C,
                             cudaFuncAttributeMaxDynamicSharedMemorySize,
                             DSMEM_BYTES);
        attr_set = true;
    }

    dim3 grid1(96, NSPLIT);
    gates_mma_sk<<<grid1, 256>>>(x, Wq, Wk, Wv, Wi, Wf, Wo);

    gates_reduce<<<384, 256>>>(bq, bk, bv, bi, bf, bo);

    dim3 grid2(16, 64);
    update_C<<<grid2, 256, DSMEM_BYTES>>>(Cprev, nprev, out_C, out_h, out_n);
}

// round 13
// speedup vs baseline: 1.0044x; 1.0044x over previous
#include <cuda_runtime.h>
#include <math.h>
#include <stdint.h>

// Problem constants
#define B_   64
#define IN_  512
#define M_   1024
#define NG   6          // q,k,v,i,f,o
#define NSPLIT 4
#define KSL  (IN_ / NSPLIT)   // 128
#define BM   (B_ * M_)
#define NITEMS 1024           // 64 batches x 16 chunks
#define PBLOCKS 296           // 2 per SM x 148 SMs (persistent)

// scratch
__device__ float g_gates[NG * B_ * M_];          // [gate][b][m]
__device__ float g_part[NSPLIT * B_ * NG * M_];  // [s][b][n_global]
__device__ unsigned int g_ctr;                   // persistent work counter

__device__ __forceinline__ float sigmoidf_(float v) {
    return 1.f / (1.f + __expf(-v));
}

// ---------------------------------------------------------------------------
// TF32 helpers
// ---------------------------------------------------------------------------
__device__ __forceinline__ uint32_t f2tf32(float f) {
    uint32_t u;
    asm("cvt.rna.tf32.f32 %0, %1;" : "=r"(u) : "f"(f));
    return u;
}

__device__ __forceinline__ void mma_tf32(float* c, const uint32_t* a, const uint32_t* b) {
    asm("mma.sync.aligned.m16n8k8.row.col.f32.tf32.tf32.f32 "
        "{%0,%1,%2,%3},{%4,%5,%6,%7},{%8,%9},{%0,%1,%2,%3};"
        : "+f"(c[0]), "+f"(c[1]), "+f"(c[2]), "+f"(c[3])
        : "r"(a[0]), "r"(a[1]), "r"(a[2]), "r"(a[3]),
          "r"(b[0]), "r"(b[1]));
}

// ---------------------------------------------------------------------------
// Kernel 1a: split-K TF32 tensor-core GEMM partials (R10 version, 10.6us)
// grid = (96, 4). Block tile 64x64x32 double-buffered, warp grid 2m x 4n.
// ---------------------------------------------------------------------------
__global__ __launch_bounds__(256)
void gates_mma_sk(const float* __restrict__ x,
                  const float* __restrict__ Wq, const float* __restrict__ Wk,
                  const float* __restrict__ Wv, const float* __restrict__ Wi,
                  const float* __restrict__ Wf, const float* __restrict__ Wo)
{
    const int n_global0 = blockIdx.x * 64;
    const int gate      = n_global0 >> 10;
    const int n_local0  = n_global0 & (M_ - 1);
    const int s         = blockIdx.y;
    const int k_base    = s * KSL;

    const float* W;
    switch (gate) {
        case 0: W = Wq; break;
        case 1: W = Wk; break;
        case 2: W = Wv; break;
        case 3: W = Wi; break;
        case 4: W = Wf; break;
        default: W = Wo; break;
    }

    __shared__ uint32_t Xs[2][64][36];
    __shared__ uint32_t Ws[2][64][36];

    const int tid  = threadIdx.x;
    const int wid  = tid >> 5;
    const int lane = tid & 31;
    const int g    = lane >> 2;
    const int tig  = lane & 3;
    const int warp_m = wid & 1;
    const int warp_n = wid >> 1;

    const int lrow0 = tid >> 3;
    const int lrow1 = lrow0 + 32;
    const int lcol  = (tid & 7) * 4;

    const float* xg0 = x + lrow0 * IN_ + k_base + lcol;
    const float* xg1 = x + lrow1 * IN_ + k_base + lcol;
    const float* wg0 = W + (n_local0 + lrow0) * IN_ + k_base + lcol;
    const float* wg1 = W + (n_local0 + lrow1) * IN_ + k_base + lcol;

    float acc[2][2][4];
    #pragma unroll
    for (int mt = 0; mt < 2; mt++)
        #pragma unroll
        for (int nt = 0; nt < 2; nt++)
            #pragma unroll
            for (int e = 0; e < 4; e++) acc[mt][nt][e] = 0.f;

    float4 xr0, xr1, wr0, wr1;
    xr0 = *(const float4*)xg0;
    xr1 = *(const float4*)xg1;
    wr0 = *(const float4*)wg0;
    wr1 = *(const float4*)wg1;

    {
        uint4 u;
        u.x = f2tf32(xr0.x); u.y = f2tf32(xr0.y); u.z = f2tf32(xr0.z); u.w = f2tf32(xr0.w);
        *(uint4*)&Xs[0][lrow0][lcol] = u;
        u.x = f2tf32(xr1.x); u.y = f2tf32(xr1.y); u.z = f2tf32(xr1.z); u.w = f2tf32(xr1.w);
        *(uint4*)&Xs[0][lrow1][lcol] = u;
        u.x = f2tf32(wr0.x); u.y = f2tf32(wr0.y); u.z = f2tf32(wr0.z); u.w = f2tf32(wr0.w);
        *(uint4*)&Ws[0][lrow0][lcol] = u;
        u.x = f2tf32(wr1.x); u.y = f2tf32(wr1.y); u.z = f2tf32(wr1.z); u.w = f2tf32(wr1.w);
        *(uint4*)&Ws[0][lrow1][lcol] = u;
    }
    __syncthreads();

    int buf = 0;
    #pragma unroll 1
    for (int it = 0; it < KSL / 32; it++) {
        if (it < KSL / 32 - 1) {
            const int k0 = (it + 1) * 32;
            xr0 = *(const float4*)(xg0 + k0);
            xr1 = *(const float4*)(xg1 + k0);
            wr0 = *(const float4*)(wg0 + k0);
            wr1 = *(const float4*)(wg1 + k0);
        }

        #pragma unroll
        for (int ks = 0; ks < 4; ks++) {
            const int ko = ks * 8;
            uint32_t af[2][4];
            #pragma unroll
            for (int mt = 0; mt < 2; mt++) {
                const int r = warp_m * 32 + mt * 16 + g;
                af[mt][0] = Xs[buf][r][ko + tig];
                af[mt][1] = Xs[buf][r + 8][ko + tig];
                af[mt][2] = Xs[buf][r][ko + tig + 4];
                af[mt][3] = Xs[buf][r + 8][ko + tig + 4];
            }
            uint32_t bfr[2][2];
            #pragma unroll
            for (int nt = 0; nt < 2; nt++) {
                const int c = warp_n * 16 + nt * 8 + g;
                bfr[nt][0] = Ws[buf][c][ko + tig];
                bfr[nt][1] = Ws[buf][c][ko + tig + 4];
            }
            #pragma unroll
            for (int mt = 0; mt < 2; mt++)
                #pragma unroll
                for (int nt = 0; nt < 2; nt++)
                    mma_tf32(acc[mt][nt], af[mt], bfr[nt]);
        }

        if (it < KSL / 32 - 1) {
            const int nb = buf ^ 1;
            uint4 u;
            u.x = f2tf32(xr0.x); u.y = f2tf32(xr0.y); u.z = f2tf32(xr0.z); u.w = f2tf32(xr0.w);
            *(uint4*)&Xs[nb][lrow0][lcol] = u;
            u.x = f2tf32(xr1.x); u.y = f2tf32(xr1.y); u.z = f2tf32(xr1.z); u.w = f2tf32(xr1.w);
            *(uint4*)&Xs[nb][lrow1][lcol] = u;
            u.x = f2tf32(wr0.x); u.y = f2tf32(wr0.y); u.z = f2tf32(wr0.z); u.w = f2tf32(wr0.w);
            *(uint4*)&Ws[nb][lrow0][lcol] = u;
            u.x = f2tf32(wr1.x); u.y = f2tf32(wr1.y); u.z = f2tf32(wr1.z); u.w = f2tf32(wr1.w);
            *(uint4*)&Ws[nb][lrow1][lcol] = u;
            __syncthreads();
            buf = nb;
        }
    }

    float* outp = g_part + (size_t)s * ((size_t)B_ * NG * M_);
    #pragma unroll
    for (int mt = 0; mt < 2; mt++) {
        const int r0 = warp_m * 32 + mt * 16 + g;
        #pragma unroll
        for (int nt = 0; nt < 2; nt++) {
            const int ncol = n_global0 + warp_n * 16 + nt * 8 + 2 * tig;
            *(float2*)&outp[(size_t)r0 * (NG * M_) + ncol] =
                make_float2(acc[mt][nt][0], acc[mt][nt][1]);
            *(float2*)&outp[(size_t)(r0 + 8) * (NG * M_) + ncol] =
                make_float2(acc[mt][nt][2], acc[mt][nt][3]);
        }
    }
}

// ---------------------------------------------------------------------------
// Kernel 1b: reduce partials + bias + activation -> g_gates[gate][b][m]
// Also resets the persistent work counter for update_C.
// ---------------------------------------------------------------------------
__global__ __launch_bounds__(256)
void gates_reduce(const float* __restrict__ bq, const float* __restrict__ bk,
                  const float* __restrict__ bv, const float* __restrict__ bi,
                  const float* __restrict__ bf, const float* __restrict__ bo)
{
    const int idx = blockIdx.x * 256 + threadIdx.x;
    if (idx == 0) g_ctr = 0;                       // reset persistent counter

    const int b   = idx / (NG * M_ / 4);
    const int c4  = idx % (NG * M_ / 4);
    const int n   = c4 * 4;
    const int gate = n >> 10;
    const int nl   = n & (M_ - 1);

    const float* bias;
    switch (gate) {
        case 0: bias = bq; break;
        case 1: bias = bk; break;
        case 2: bias = bv; break;
        case 3: bias = bi; break;
        case 4: bias = bf; break;
        default: bias = bo; break;
    }

    float4 acc = *(const float4*)&g_part[((size_t)0 * B_ + b) * (NG * M_) + n];
    #pragma unroll
    for (int s = 1; s < NSPLIT; s++) {
        float4 p = *(const float4*)&g_part[((size_t)s * B_ + b) * (NG * M_) + n];
        acc.x += p.x; acc.y += p.y; acc.z += p.z; acc.w += p.w;
    }
    const float4 bv4 = *(const float4*)&bias[nl];
    acc.x += bv4.x; acc.y += bv4.y; acc.z += bv4.z; acc.w += bv4.w;

    if (gate == 1) {
        acc.x *= 0.03125f; acc.y *= 0.03125f; acc.z *= 0.03125f; acc.w *= 0.03125f;
    } else if (gate == 3) {
        acc.x = __expf(acc.x); acc.y = __expf(acc.y);
        acc.z = __expf(acc.z); acc.w = __expf(acc.w);
    } else if (gate >= 4) {
        acc.x = sigmoidf_(acc.x);
        acc.y = sigmoidf_(acc.y);
        acc.z = sigmoidf_(acc.z);
        acc.w = sigmoidf_(acc.w);
    }
    *(float4*)&g_gates[(size_t)gate * BM + b * M_ + nl] = acc;
}

// ---------------------------------------------------------------------------
// Kernel 2 (persistent): C_t update + h_tilde + n_t + denom + h_t.
// grid = 296 blocks (2/SM); dynamic work items via g_ctr.
// item = b*16 + chunk  (b = item>>4, chunk = item&15) -> consecutive items
// share batch b (gate data L2-hot).
// Per item: prologue (stage k/q, n_t+denom) then the R7-measured pipelined
// streaming loop over 64 rows.
// ---------------------------------------------------------------------------
__global__ __launch_bounds__(256)
void update_C(const float* __restrict__ Cprev, const float* __restrict__ nprev,
              float* __restrict__ Cout, float* __restrict__ out_h,
              float* __restrict__ out_n)
{
    __shared__ float sk[M_];
    __shared__ float sq[M_];
    __shared__ float red[8];
    __shared__ float s_inv;
    __shared__ unsigned int s_item;

    const int t    = threadIdx.x;
    const int warp = t >> 5;
    const int lane = t & 31;

    while (true) {
        if (t == 0) s_item = atomicAdd(&g_ctr, 1u);
        __syncthreads();
        const unsigned int item = s_item;
        if (item >= NITEMS) return;

        const int b     = item >> 4;      // batch
        const int chunk = item & 15;      // 64-row chunk

        const float* gq = g_gates + 0 * BM + b * M_;
        const float* gk = g_gates + 1 * BM + b * M_;
        const float* gv = g_gates + 2 * BM + b * M_;
        const float* gi = g_gates + 3 * BM + b * M_;
        const float* gf = g_gates + 4 * BM + b * M_;
        const float* go = g_gates + 5 * BM + b * M_;

        ((float4*)sk)[t] = ((const float4*)gk)[t];
        ((float4*)sq)[t] = ((const float4*)gq)[t];
        __syncthreads();

        // --- denom prologue: n_t = f*n_prev + i*k ; part = n_t . q ---
        {
            float4 f4 = ((const float4*)gf)[t];
            float4 i4 = ((const float4*)gi)[t];
            float4 p4 = ((const float4*)(nprev + b * M_))[t];
            float4 k4 = ((const float4*)sk)[t];
            float4 q4 = ((const float4*)sq)[t];
            float4 n4;
            n4.x = fmaf(f4.x, p4.x, i4.x * k4.x);
            n4.y = fmaf(f4.y, p4.y, i4.y * k4.y);
            n4.z = fmaf(f4.z, p4.z, i4.z * k4.z);
            n4.w = fmaf(f4.w, p4.w, i4.w * k4.w);
            if (chunk == 0)
                ((float4*)(out_n + b * M_))[t] = n4;
            float part = n4.x * q4.x + n4.y * q4.y + n4.z * q4.z + n4.w * q4.w;
            #pragma unroll
            for (int off = 16; off; off >>= 1)
                part += __shfl_xor_sync(0xffffffffu, part, off);
            if (lane == 0) red[warp] = part;
            __syncthreads();
            if (t == 0) {
                float d = red[0] + red[1] + red[2] + red[3]
                        + red[4] + red[5] + red[6] + red[7];
                s_inv = 1.0f / fmaxf(d, 1.0f);
            }
            __syncthreads();
        }
        const float inv = s_inv;

        const float4* sk4 = (const float4*)sk;
        const float4* sq4 = (const float4*)sq;

        const int m_base = chunk * 64 + warp;

        // --- pipelined streaming loop over 8 rows per warp ---
        float4 cur[8], nxt[8];
        int m = m_base;
        float fm = gf[m];
        float cm = gi[m] * gv[m];
        {
            const float4* cp = (const float4*)(Cprev + ((size_t)b * M_ + m) * M_);
            #pragma unroll
            for (int j = 0; j < 8; j++) cur[j] = __ldcs(cp + j * 32 + lane);
        }

        #pragma unroll
        for (int r = 0; r < 8; r++) {
            float fmn = 0.f, cmn = 0.f;
            if (r < 7) {
                const int mn = m_base + (r + 1) * 8;
                fmn = gf[mn];
                cmn = gi[mn] * gv[mn];
                const float4* cpn = (const float4*)(Cprev + ((size_t)b * M_ + mn) * M_);
                #pragma unroll
                for (int j = 0; j < 8; j++) nxt[j] = __ldcs(cpn + j * 32 + lane);
            }

            float4* co = (float4*)(Cout + ((size_t)b * M_ + m) * M_);
            float dot0 = 0.f, dot1 = 0.f;
            #pragma unroll
            for (int j = 0; j < 8; j++) {
                const int n4 = j * 32 + lane;
                float4 kk = sk4[n4];
                float4 qq = sq4[n4];
                float4 o;
                o.x = fmaf(fm, cur[j].x, cm * kk.x);
                o.y = fmaf(fm, cur[j].y, cm * kk.y);
                o.z = fmaf(fm, cur[j].z, cm * kk.z);
                o.w = fmaf(fm, cur[j].w, cm * kk.w);
                __stcs(co + n4, o);
                if (j & 1) {
                    dot1 = fmaf(o.x, qq.x, dot1);
                    dot1 = fmaf(o.y, qq.y, dot1);
                    dot1 = fmaf(o.z, qq.z, dot1);
                    dot1 = fmaf(o.w, qq.w, dot1);
                } else {
                    dot0 = fmaf(o.x, qq.x, dot0);
                    dot0 = fmaf(o.y, qq.y, dot0);
                    dot0 = fmaf(o.z, qq.z, dot0);
                    dot0 = fmaf(o.w, qq.w, dot0);
                }
            }
            float dot = dot0 + dot1;
            #pragma unroll
            for (int off = 16; off; off >>= 1)
                dot += __shfl_xor_sync(0xffffffffu, dot, off);
            if (lane == 0)
                out_h[b * M_ + m] = go[m] * dot * inv;

            m = m_base + (r + 1) * 8;
            fm = fmn;
            cm = cmn;
            #pragma unroll
            for (int j = 0; j < 8; j++) cur[j] = nxt[j];
        }

        __syncthreads();   // sk/sq reuse safety before next item
    }
}

// ---------------------------------------------------------------------------
// Launch. Inputs (metadata order):
// 0 x, 1 h_prev, 2 c_prev, 3 C_prev, 4 n_prev, 5 m_prev,
// 6 Wq, 7 bq, 8 Wk, 9 bk, 10 Wv, 11 bv, 12 Wi, 13 bi, 14 Wf, 15 bf, 16 Wo, 17 bo
// Output: concat(h_t [64*1024], C_t [64*1024*1024], n_t [64*1024])
// ---------------------------------------------------------------------------
extern "C" void kernel_launch(void* const* d_in, const int* in_sizes, int n_in,
                              void* d_out, int out_size)
{
    const float* x     = (const float*)d_in[0];
    const float* Cprev = (const float*)d_in[3];
    const float* nprev = (const float*)d_in[4];

    const float* Wq = (const float*)d_in[6];  const float* bq = (const float*)d_in[7];
    const float* Wk = (const float*)d_in[8];  const float* bk = (const float*)d_in[9];
    const float* Wv = (const float*)d_in[10]; const float* bv = (const float*)d_in[11];
    const float* Wi = (const float*)d_in[12]; const float* bi = (const float*)d_in[13];
    const float* Wf = (const float*)d_in[14]; const float* bf = (const float*)d_in[15];
    const float* Wo = (const float*)d_in[16]; const float* bo = (const float*)d_in[17];

    float* out   = (float*)d_out;
    float* out_h = out;                                    // [64*1024]
    float* out_C = out + (size_t)B_ * M_;                  // [64*1024*1024]
    float* out_n = out + (size_t)B_ * M_ + (size_t)B_ * M_ * M_;

    dim3 grid1(96, NSPLIT);
    gates_mma_sk<<<grid1, 256>>>(x, Wq, Wk, Wv, Wi, Wf, Wo);

    gates_reduce<<<384, 256>>>(bq, bk, bv, bi, bf, bo);

    update_C<<<PBLOCKS, 256>>>(Cprev, nprev, out_C, out_h, out_n);
}

// round 14
// speedup vs baseline: 1.0476x; 1.0430x over previous
#include <cuda_runtime.h>
#include <math.h>
#include <stdint.h>

// Problem constants
#define B_   64
#define IN_  512
#define M_   1024
#define NG   6          // q,k,v,i,f,o
#define NSPLIT 8
#define KSL  (IN_ / NSPLIT)   // 64
#define BM   (B_ * M_)

// scratch
__device__ float g_gates[NG * B_ * M_];          // [gate][b][m]
__device__ float g_part[NSPLIT * B_ * NG * M_];  // [s][b][n_global]

__device__ __forceinline__ float sigmoidf_(float v) {
    return 1.f / (1.f + __expf(-v));
}

// ---------------------------------------------------------------------------
// TF32 helpers
// ---------------------------------------------------------------------------
__device__ __forceinline__ uint32_t f2tf32(float f) {
    uint32_t u;
    asm("cvt.rna.tf32.f32 %0, %1;" : "=r"(u) : "f"(f));
    return u;
}

__device__ __forceinline__ void mma_tf32(float* c, const uint32_t* a, const uint32_t* b) {
    asm("mma.sync.aligned.m16n8k8.row.col.f32.tf32.tf32.f32 "
        "{%0,%1,%2,%3},{%4,%5,%6,%7},{%8,%9},{%0,%1,%2,%3};"
        : "+f"(c[0]), "+f"(c[1]), "+f"(c[2]), "+f"(c[3])
        : "r"(a[0]), "r"(a[1]), "r"(a[2]), "r"(a[3]),
          "r"(b[0]), "r"(b[1]));
}

// ---------------------------------------------------------------------------
// Kernel 1a: split-K TF32 tensor-core GEMM partials.
// grid = (96, 8): bx -> 64-wide column tile, by -> 64-wide K slice.
// Block tile 64x64x32 double-buffered (2 iterations), warp grid 2m x 4n.
// 768 blocks -> ~5 blocks/SM resident for latency hiding.
// ---------------------------------------------------------------------------
__global__ __launch_bounds__(256)
void gates_mma_sk(const float* __restrict__ x,
                  const float* __restrict__ Wq, const float* __restrict__ Wk,
                  const float* __restrict__ Wv, const float* __restrict__ Wi,
                  const float* __restrict__ Wf, const float* __restrict__ Wo)
{
    const int n_global0 = blockIdx.x * 64;
    const int gate      = n_global0 >> 10;
    const int n_local0  = n_global0 & (M_ - 1);
    const int s         = blockIdx.y;
    const int k_base    = s * KSL;

    const float* W;
    switch (gate) {
        case 0: W = Wq; break;
        case 1: W = Wk; break;
        case 2: W = Wv; break;
        case 3: W = Wi; break;
        case 4: W = Wf; break;
        default: W = Wo; break;
    }

    __shared__ uint32_t Xs[2][64][36];
    __shared__ uint32_t Ws[2][64][36];

    const int tid  = threadIdx.x;
    const int wid  = tid >> 5;
    const int lane = tid & 31;
    const int g    = lane >> 2;
    const int tig  = lane & 3;
    const int warp_m = wid & 1;
    const int warp_n = wid >> 1;

    const int lrow0 = tid >> 3;
    const int lrow1 = lrow0 + 32;
    const int lcol  = (tid & 7) * 4;

    const float* xg0 = x + lrow0 * IN_ + k_base + lcol;
    const float* xg1 = x + lrow1 * IN_ + k_base + lcol;
    const float* wg0 = W + (n_local0 + lrow0) * IN_ + k_base + lcol;
    const float* wg1 = W + (n_local0 + lrow1) * IN_ + k_base + lcol;

    float acc[2][2][4];
    #pragma unroll
    for (int mt = 0; mt < 2; mt++)
        #pragma unroll
        for (int nt = 0; nt < 2; nt++)
            #pragma unroll
            for (int e = 0; e < 4; e++) acc[mt][nt][e] = 0.f;

    float4 xr0, xr1, wr0, wr1;
    xr0 = *(const float4*)xg0;
    xr1 = *(const float4*)xg1;
    wr0 = *(const float4*)wg0;
    wr1 = *(const float4*)wg1;

    {
        uint4 u;
        u.x = f2tf32(xr0.x); u.y = f2tf32(xr0.y); u.z = f2tf32(xr0.z); u.w = f2tf32(xr0.w);
        *(uint4*)&Xs[0][lrow0][lcol] = u;
        u.x = f2tf32(xr1.x); u.y = f2tf32(xr1.y); u.z = f2tf32(xr1.z); u.w = f2tf32(xr1.w);
        *(uint4*)&Xs[0][lrow1][lcol] = u;
        u.x = f2tf32(wr0.x); u.y = f2tf32(wr0.y); u.z = f2tf32(wr0.z); u.w = f2tf32(wr0.w);
        *(uint4*)&Ws[0][lrow0][lcol] = u;
        u.x = f2tf32(wr1.x); u.y = f2tf32(wr1.y); u.z = f2tf32(wr1.z); u.w = f2tf32(wr1.w);
        *(uint4*)&Ws[0][lrow1][lcol] = u;
    }
    __syncthreads();

    int buf = 0;
    #pragma unroll 1
    for (int it = 0; it < KSL / 32; it++) {
        if (it < KSL / 32 - 1) {
            const int k0 = (it + 1) * 32;
            xr0 = *(const float4*)(xg0 + k0);
            xr1 = *(const float4*)(xg1 + k0);
            wr0 = *(const float4*)(wg0 + k0);
            wr1 = *(const float4*)(wg1 + k0);
        }

        #pragma unroll
        for (int ks = 0; ks < 4; ks++) {
            const int ko = ks * 8;
            uint32_t af[2][4];
            #pragma unroll
            for (int mt = 0; mt < 2; mt++) {
                const int r = warp_m * 32 + mt * 16 + g;
                af[mt][0] = Xs[buf][r][ko + tig];
                af[mt][1] = Xs[buf][r + 8][ko + tig];
                af[mt][2] = Xs[buf][r][ko + tig + 4];
                af[mt][3] = Xs[buf][r + 8][ko + tig + 4];
            }
            uint32_t bfr[2][2];
            #pragma unroll
            for (int nt = 0; nt < 2; nt++) {
                const int c = warp_n * 16 + nt * 8 + g;
                bfr[nt][0] = Ws[buf][c][ko + tig];
                bfr[nt][1] = Ws[buf][c][ko + tig + 4];
            }
            #pragma unroll
            for (int mt = 0; mt < 2; mt++)
                #pragma unroll
                for (int nt = 0; nt < 2; nt++)
                    mma_tf32(acc[mt][nt], af[mt], bfr[nt]);
        }

        if (it < KSL / 32 - 1) {
            const int nb = buf ^ 1;
            uint4 u;
            u.x = f2tf32(xr0.x); u.y = f2tf32(xr0.y); u.z = f2tf32(xr0.z); u.w = f2tf32(xr0.w);
            *(uint4*)&Xs[nb][lrow0][lcol] = u;
            u.x = f2tf32(xr1.x); u.y = f2tf32(xr1.y); u.z = f2tf32(xr1.z); u.w = f2tf32(xr1.w);
            *(uint4*)&Xs[nb][lrow1][lcol] = u;
            u.x = f2tf32(wr0.x); u.y = f2tf32(wr0.y); u.z = f2tf32(wr0.z); u.w = f2tf32(wr0.w);
            *(uint4*)&Ws[nb][lrow0][lcol] = u;
            u.x = f2tf32(wr1.x); u.y = f2tf32(wr1.y); u.z = f2tf32(wr1.z); u.w = f2tf32(wr1.w);
            *(uint4*)&Ws[nb][lrow1][lcol] = u;
            __syncthreads();
            buf = nb;
        }
    }

    float* outp = g_part + (size_t)s * ((size_t)B_ * NG * M_);
    #pragma unroll
    for (int mt = 0; mt < 2; mt++) {
        const int r0 = warp_m * 32 + mt * 16 + g;
        #pragma unroll
        for (int nt = 0; nt < 2; nt++) {
            const int ncol = n_global0 + warp_n * 16 + nt * 8 + 2 * tig;
            *(float2*)&outp[(size_t)r0 * (NG * M_) + ncol] =
                make_float2(acc[mt][nt][0], acc[mt][nt][1]);
            *(float2*)&outp[(size_t)(r0 + 8) * (NG * M_) + ncol] =
                make_float2(acc[mt][nt][2], acc[mt][nt][3]);
        }
    }
}

// ---------------------------------------------------------------------------
// Kernel 1b: reduce partials + bias + activation -> g_gates[gate][b][m]
// ---------------------------------------------------------------------------
__global__ __launch_bounds__(256)
void gates_reduce(const float* __restrict__ bq, const float* __restrict__ bk,
                  const float* __restrict__ bv, const float* __restrict__ bi,
                  const float* __restrict__ bf, const float* __restrict__ bo)
{
    const int idx = blockIdx.x * 256 + threadIdx.x;
    const int b   = idx / (NG * M_ / 4);
    const int c4  = idx % (NG * M_ / 4);
    const int n   = c4 * 4;
    const int gate = n >> 10;
    const int nl   = n & (M_ - 1);

    const float* bias;
    switch (gate) {
        case 0: bias = bq; break;
        case 1: bias = bk; break;
        case 2: bias = bv; break;
        case 3: bias = bi; break;
        case 4: bias = bf; break;
        default: bias = bo; break;
    }

    float4 acc = *(const float4*)&g_part[((size_t)0 * B_ + b) * (NG * M_) + n];
    #pragma unroll
    for (int s = 1; s < NSPLIT; s++) {
        float4 p = *(const float4*)&g_part[((size_t)s * B_ + b) * (NG * M_) + n];
        acc.x += p.x; acc.y += p.y; acc.z += p.z; acc.w += p.w;
    }
    const float4 bv4 = *(const float4*)&bias[nl];
    acc.x += bv4.x; acc.y += bv4.y; acc.z += bv4.z; acc.w += bv4.w;

    if (gate == 1) {
        acc.x *= 0.03125f; acc.y *= 0.03125f; acc.z *= 0.03125f; acc.w *= 0.03125f;
    } else if (gate == 3) {
        acc.x = __expf(acc.x); acc.y = __expf(acc.y);
        acc.z = __expf(acc.z); acc.w = __expf(acc.w);
    } else if (gate >= 4) {
        acc.x = sigmoidf_(acc.x);
        acc.y = sigmoidf_(acc.y);
        acc.z = sigmoidf_(acc.z);
        acc.w = sigmoidf_(acc.w);
    }
    *(float4*)&g_gates[(size_t)gate * BM + b * M_ + nl] = acc;
}

// ---------------------------------------------------------------------------
// Kernel 2 (R10/R7 version, measured 82.2us — DO NOT TOUCH):
// C_t update + h_tilde + n_t + denom + h_t. grid = (16, 64).
// Cross-row software pipeline: row r+1's 8 streaming loads issued before
// row r's compute/store/reduce.
// ---------------------------------------------------------------------------
__global__ __launch_bounds__(256)
void update_C(const float* __restrict__ Cprev, const float* __restrict__ nprev,
              float* __restrict__ Cout, float* __restrict__ out_h,
              float* __restrict__ out_n)
{
    const int b = blockIdx.y;
    __shared__ float sk[M_];
    __shared__ float sq[M_];
    __shared__ float red[8];
    __shared__ float s_inv;

    const float* gq = g_gates + 0 * BM + b * M_;
    const float* gk = g_gates + 1 * BM + b * M_;
    ((float4*)sk)[threadIdx.x] = ((const float4*)gk)[threadIdx.x];
    ((float4*)sq)[threadIdx.x] = ((const float4*)gq)[threadIdx.x];

    const int warp = threadIdx.x >> 5;
    const int lane = threadIdx.x & 31;
    const float* gv = g_gates + 2 * BM + b * M_;
    const float* gi = g_gates + 3 * BM + b * M_;
    const float* gf = g_gates + 4 * BM + b * M_;
    const float* go = g_gates + 5 * BM + b * M_;

    __syncthreads();

    // --- denom prologue: n_t = f*n_prev + i*k ; part = n_t . q ---
    {
        const int t = threadIdx.x;
        float4 f4 = ((const float4*)gf)[t];
        float4 i4 = ((const float4*)gi)[t];
        float4 p4 = ((const float4*)(nprev + b * M_))[t];
        float4 k4 = ((const float4*)sk)[t];
        float4 q4 = ((const float4*)sq)[t];
        float4 n4;
        n4.x = fmaf(f4.x, p4.x, i4.x * k4.x);
        n4.y = fmaf(f4.y, p4.y, i4.y * k4.y);
        n4.z = fmaf(f4.z, p4.z, i4.z * k4.z);
        n4.w = fmaf(f4.w, p4.w, i4.w * k4.w);
        if (blockIdx.x == 0)
            ((float4*)(out_n + b * M_))[t] = n4;
        float part = n4.x * q4.x + n4.y * q4.y + n4.z * q4.z + n4.w * q4.w;
        #pragma unroll
        for (int off = 16; off; off >>= 1)
            part += __shfl_xor_sync(0xffffffffu, part, off);
        if (lane == 0) red[warp] = part;
        __syncthreads();
        if (threadIdx.x == 0) {
            float d = red[0] + red[1] + red[2] + red[3]
                    + red[4] + red[5] + red[6] + red[7];
            s_inv = 1.0f / fmaxf(d, 1.0f);
        }
        __syncthreads();
    }
    const float inv = s_inv;

    const float4* sk4 = (const float4*)sk;
    const float4* sq4 = (const float4*)sq;

    const int m_base = blockIdx.x * 64 + warp;

    float4 cur[8], nxt[8];
    int m = m_base;
    float fm = gf[m];
    float cm = gi[m] * gv[m];
    {
        const float4* cp = (const float4*)(Cprev + ((size_t)b * M_ + m) * M_);
        #pragma unroll
        for (int j = 0; j < 8; j++) cur[j] = __ldcs(cp + j * 32 + lane);
    }

    #pragma unroll
    for (int r = 0; r < 8; r++) {
        float fmn = 0.f, cmn = 0.f;
        if (r < 7) {
            const int mn = m_base + (r + 1) * 8;
            fmn = gf[mn];
            cmn = gi[mn] * gv[mn];
            const float4* cpn = (const float4*)(Cprev + ((size_t)b * M_ + mn) * M_);
            #pragma unroll
            for (int j = 0; j < 8; j++) nxt[j] = __ldcs(cpn + j * 32 + lane);
        }

        float4* co = (float4*)(Cout + ((size_t)b * M_ + m) * M_);
        float dot0 = 0.f, dot1 = 0.f;
        #pragma unroll
        for (int j = 0; j < 8; j++) {
            const int n4 = j * 32 + lane;
            float4 kk = sk4[n4];
            float4 qq = sq4[n4];
            float4 o;
            o.x = fmaf(fm, cur[j].x, cm * kk.x);
            o.y = fmaf(fm, cur[j].y, cm * kk.y);
            o.z = fmaf(fm, cur[j].z, cm * kk.z);
            o.w = fmaf(fm, cur[j].w, cm * kk.w);
            __stcs(co + n4, o);
            if (j & 1) {
                dot1 = fmaf(o.x, qq.x, dot1);
                dot1 = fmaf(o.y, qq.y, dot1);
                dot1 = fmaf(o.z, qq.z, dot1);
                dot1 = fmaf(o.w, qq.w, dot1);
            } else {
                dot0 = fmaf(o.x, qq.x, dot0);
                dot0 = fmaf(o.y, qq.y, dot0);
                dot0 = fmaf(o.z, qq.z, dot0);
                dot0 = fmaf(o.w, qq.w, dot0);
            }
        }
        float dot = dot0 + dot1;
        #pragma unroll
        for (int off = 16; off; off >>= 1)
            dot += __shfl_xor_sync(0xffffffffu, dot, off);
        if (lane == 0)
            out_h[b * M_ + m] = go[m] * dot * inv;

        m = m_base + (r + 1) * 8;
        fm = fmn;
        cm = cmn;
        #pragma unroll
        for (int j = 0; j < 8; j++) cur[j] = nxt[j];
    }
}

// ---------------------------------------------------------------------------
// Launch. Inputs (metadata order):
// 0 x, 1 h_prev, 2 c_prev, 3 C_prev, 4 n_prev, 5 m_prev,
// 6 Wq, 7 bq, 8 Wk, 9 bk, 10 Wv, 11 bv, 12 Wi, 13 bi, 14 Wf, 15 bf, 16 Wo, 17 bo
// Output: concat(h_t [64*1024], C_t [64*1024*1024], n_t [64*1024])
// ---------------------------------------------------------------------------
extern "C" void kernel_launch(void* const* d_in, const int* in_sizes, int n_in,
                              void* d_out, int out_size)
{
    const float* x     = (const float*)d_in[0];
    const float* Cprev = (const float*)d_in[3];
    const float* nprev = (const float*)d_in[4];

    const float* Wq = (const float*)d_in[6];  const float* bq = (const float*)d_in[7];
    const float* Wk = (const float*)d_in[8];  const float* bk = (const float*)d_in[9];
    const float* Wv = (const float*)d_in[10]; const float* bv = (const float*)d_in[11];
    const float* Wi = (const float*)d_in[12]; const float* bi = (const float*)d_in[13];
    const float* Wf = (const float*)d_in[14]; const float* bf = (const float*)d_in[15];
    const float* Wo = (const float*)d_in[16]; const float* bo = (const float*)d_in[17];

    float* out   = (float*)d_out;
    float* out_h = out;                                    // [64*1024]
    float* out_C = out + (size_t)B_ * M_;                  // [64*1024*1024]
    float* out_n = out + (size_t)B_ * M_ + (size_t)B_ * M_ * M_;

    dim3 grid1(96, NSPLIT);
    gates_mma_sk<<<grid1, 256>>>(x, Wq, Wk, Wv, Wi, Wf, Wo);

    gates_reduce<<<384, 256>>>(bq, bk, bv, bi, bf, bo);

    dim3 grid2(16, 64);
    update_C<<<grid2, 256>>>(Cprev, nprev, out_C, out_h, out_n);
}